// round 3
// baseline (speedup 1.0000x reference)
#include <cuda_runtime.h>
#include <cuda_bf16.h>
#include <cstdint>

// ---------------- problem constants ----------------
#define M_TOTAL 8192
#define N_TOTAL 4096
#define K_IN    4096

#define BM 128
#define BN 64
#define BK 64                         // s8 k-bytes per stage chunk
#define NK (K_IN / BK)                // 64
#define STAGES 4
#define APITCH 80                     // bytes per smem row (64 data + 16 pad)
#define A_TILE (128 * APITCH)         // 10240 B per limb tile
#define B_TILE (64 * APITCH)          // 5120 B
#define STAGE_BYTES (3 * A_TILE + B_TILE)      // 35840
#define SMEM_BYTES (STAGES * STAGE_BYTES)      // 143360

#define PLANE ((size_t)M_TOTAL * K_IN)         // bytes per limb plane

// ---------------- scratch (device globals: allocation-free) ----------------
__device__ int8_t g_A8[3 * PLANE];             // 100 MB: 3 limb planes of X=round(x*2^20)
__device__ int8_t g_W8[(size_t)N_TOTAL * K_IN];// 16.7 MB: sign(W) as s8

// ---------------- helpers ----------------
static __device__ __forceinline__ void cpa16(uint32_t dst, const void* src) {
    asm volatile("cp.async.cg.shared.global [%0], [%1], 16;" :: "r"(dst), "l"(src));
}
static __device__ __forceinline__ void ldsm4(uint32_t* r, uint32_t addr) {
    asm volatile("ldmatrix.sync.aligned.m8n8.x4.shared.b16 {%0,%1,%2,%3}, [%4];"
                 : "=r"(r[0]), "=r"(r[1]), "=r"(r[2]), "=r"(r[3]) : "r"(addr));
}
static __device__ __forceinline__ void imma16832(int* c, const uint32_t* a, const uint32_t* b) {
    asm volatile(
        "mma.sync.aligned.m16n8k32.row.col.s32.s8.s8.s32 "
        "{%0,%1,%2,%3}, {%4,%5,%6,%7}, {%8,%9}, {%0,%1,%2,%3};"
        : "+r"(c[0]), "+r"(c[1]), "+r"(c[2]), "+r"(c[3])
        : "r"(a[0]), "r"(a[1]), "r"(a[2]), "r"(a[3]), "r"(b[0]), "r"(b[1]));
}
static __device__ __forceinline__ float sgnf(float z) {
    return (z > 0.f) ? 1.f : ((z < 0.f) ? -1.f : 0.f);
}

// ---------------- prep kernels ----------------
// X = round(x * 2^20), exact 3-digit base-256 balanced decomposition:
// X = d0*65536 + d1*256 + d2, digits in [-128,127].
__global__ void prep_x8(const float* __restrict__ x) {
    const int t   = blockIdx.x * blockDim.x + threadIdx.x;  // 0..1023
    const int row = blockIdx.y;
    const int col = t * 4;
    float4 v = *reinterpret_cast<const float4*>(&x[(size_t)row * K_IN + col]);
    float vv[4] = {v.x, v.y, v.z, v.w};
    uint32_t u0 = 0, u1 = 0, u2 = 0;
    #pragma unroll
    for (int j = 0; j < 4; j++) {
        int X  = __float2int_rn(vv[j] * 1048576.0f);
        int d2 = ((X & 255) ^ 128) - 128;
        int X1 = (X - d2) >> 8;
        int d1 = ((X1 & 255) ^ 128) - 128;
        int d0 = (X1 - d1) >> 8;
        u0 |= (uint32_t)(d0 & 255) << (8 * j);
        u1 |= (uint32_t)(d1 & 255) << (8 * j);
        u2 |= (uint32_t)(d2 & 255) << (8 * j);
    }
    const size_t o = ((size_t)row * K_IN + col) >> 2;
    reinterpret_cast<uint32_t*>(g_A8)[o]                      = u0;
    reinterpret_cast<uint32_t*>(g_A8 + PLANE)[o]              = u1;
    reinterpret_cast<uint32_t*>(g_A8 + 2 * PLANE)[o]          = u2;
}

__global__ void prep_w8(const float* __restrict__ w) {
    const size_t idx = (size_t)blockIdx.x * blockDim.x + threadIdx.x;
    float4 v = *reinterpret_cast<const float4*>(&w[idx * 4]);
    float vv[4] = {v.x, v.y, v.z, v.w};
    uint32_t u = 0;
    #pragma unroll
    for (int j = 0; j < 4; j++) {
        int s = (vv[j] > 0.f) ? 1 : ((vv[j] < 0.f) ? -1 : 0);
        u |= (uint32_t)(s & 255) << (8 * j);
    }
    reinterpret_cast<uint32_t*>(g_W8)[idx] = u;
}

// ---------------- GEMM kernel (mma.sync s8, s32 accum, 3 limb accumulators) ----------------
__global__ void __launch_bounds__(256)
binlin_gemm(const float* __restrict__ bias, float* __restrict__ out) {
    extern __shared__ __align__(16) char smem[];
    const uint32_t su = (uint32_t)__cvta_generic_to_shared(smem);

    const int tid  = threadIdx.x;
    const int wid  = tid >> 5;
    const int lane = tid & 31;
    const int wm = (wid >> 1) * 32;   // warp m offset: 0..96
    const int wn = (wid & 1) * 32;    // warp n offset: 0 or 32

    const int m_base = blockIdx.y * BM;
    const int n_base = blockIdx.x * BN;

    int acc[3][2][4][4];
    #pragma unroll
    for (int l = 0; l < 3; l++)
        #pragma unroll
        for (int mi = 0; mi < 2; mi++)
            #pragma unroll
            for (int ni = 0; ni < 4; ni++)
                #pragma unroll
                for (int j = 0; j < 4; j++) acc[l][mi][ni][j] = 0;

    // ldmatrix lane mapping (shared by A x4 and B x4):
    const int lrow  = (lane & 7) + ((lane >> 3) & 1) * 8;   // 0..15
    const int lcol  = (lane >> 4) * 16;                     // 0 or 16 (bytes)

    auto load_stage = [&](int s, int kk) {
        const uint32_t sbase = su + s * STAGE_BYTES;
        const int kb = kk * BK;
        #pragma unroll
        for (int l = 0; l < 3; l++) {
            #pragma unroll
            for (int i = 0; i < 2; i++) {
                const int cid = tid + i * 256;     // 0..511
                const int row = cid >> 2;          // 0..127
                const int c   = cid & 3;
                cpa16(sbase + l * A_TILE + row * APITCH + c * 16,
                      &g_A8[l * PLANE + (size_t)(m_base + row) * K_IN + kb + c * 16]);
            }
        }
        {   // B: 64 rows x 64 B
            const int row = tid >> 2;              // 0..63
            const int c   = tid & 3;
            cpa16(sbase + 3 * A_TILE + row * APITCH + c * 16,
                  &g_W8[(size_t)(n_base + row) * K_IN + kb + c * 16]);
        }
    };

    auto compute_stage = [&](int s) {
        const uint32_t sbase = su + s * STAGE_BYTES;
        const uint32_t bbase = sbase + 3 * A_TILE;
        #pragma unroll
        for (int ks = 0; ks < 2; ks++) {
            uint32_t a[3][2][4];
            uint32_t b[4][2];
            #pragma unroll
            for (int l = 0; l < 3; l++)
                #pragma unroll
                for (int mi = 0; mi < 2; mi++) {
                    uint32_t addr = sbase + l * A_TILE +
                        (wm + mi * 16 + lrow) * APITCH + ks * 32 + lcol;
                    ldsm4(a[l][mi], addr);
                }
            #pragma unroll
            for (int p = 0; p < 2; p++) {
                uint32_t t[4];
                uint32_t addr = bbase + (wn + p * 16 + lrow) * APITCH + ks * 32 + lcol;
                ldsm4(t, addr);
                b[2 * p + 0][0] = t[0];
                b[2 * p + 1][0] = t[1];
                b[2 * p + 0][1] = t[2];
                b[2 * p + 1][1] = t[3];
            }
            #pragma unroll
            for (int l = 0; l < 3; l++)
                #pragma unroll
                for (int mi = 0; mi < 2; mi++)
                    #pragma unroll
                    for (int ni = 0; ni < 4; ni++)
                        imma16832(acc[l][mi][ni], a[l][mi], b[ni]);
        }
    };

    // ---- pipeline ----
    #pragma unroll
    for (int s = 0; s < STAGES - 1; s++) {
        load_stage(s, s);
        asm volatile("cp.async.commit_group;");
    }
    for (int kk = 0; kk < NK; kk++) {
        const int nx = kk + STAGES - 1;
        if (nx < NK) load_stage(nx & (STAGES - 1), nx);
        asm volatile("cp.async.commit_group;");
        asm volatile("cp.async.wait_group 2;");
        __syncthreads();
        compute_stage(kk & (STAGES - 1));
        __syncthreads();
    }

    // ---- epilogue: exact limb recombination, z = X_acc * 2^-20 + bias; out = sign(z) ----
    #pragma unroll
    for (int mi = 0; mi < 2; mi++) {
        #pragma unroll
        for (int ni = 0; ni < 4; ni++) {
            const int r = m_base + wm + mi * 16 + (lane >> 2);
            const int c = n_base + wn + ni * 8 + (lane & 3) * 2;
            const float b0 = bias[c];
            const float b1 = bias[c + 1];
            float2 v0, v1;
            #pragma unroll
            for (int j = 0; j < 4; j++) {
                long long tsum =
                    ((long long)acc[0][mi][ni][j] << 16) +
                    ((long long)acc[1][mi][ni][j] << 8) +
                    (long long)acc[2][mi][ni][j];
                float z = (float)((double)tsum * (1.0 / 1048576.0)) +
                          ((j & 1) ? b1 : b0);
                float sv = sgnf(z);
                if (j == 0) v0.x = sv;
                else if (j == 1) v0.y = sv;
                else if (j == 2) v1.x = sv;
                else v1.y = sv;
            }
            *reinterpret_cast<float2*>(&out[(size_t)r * N_TOTAL + c]) = v0;
            *reinterpret_cast<float2*>(&out[(size_t)(r + 8) * N_TOTAL + c]) = v1;
        }
    }
}

// ---------------- host launch ----------------
extern "C" void kernel_launch(void* const* d_in, const int* in_sizes, int n_in,
                              void* d_out, int out_size) {
    const float* x    = (const float*)d_in[0];
    const float* w    = (const float*)d_in[1];
    const float* bias = (const float*)d_in[2];
    float* out = (float*)d_out;

    prep_x8<<<dim3(K_IN / (4 * 256), M_TOTAL), 256>>>(x);
    prep_w8<<<(int)(((size_t)N_TOTAL * K_IN) / 4 / 256), 256>>>(w);

    cudaFuncSetAttribute(binlin_gemm, cudaFuncAttributeMaxDynamicSharedMemorySize,
                         SMEM_BYTES);
    binlin_gemm<<<dim3(N_TOTAL / BN, M_TOTAL / BM), 256, SMEM_BYTES>>>(bias, out);
}

// round 4
// speedup vs baseline: 3.4894x; 3.4894x over previous
#include <cuda_runtime.h>
#include <cuda_fp16.h>
#include <cstdint>

// ---------------- problem constants ----------------
#define M_TOTAL 8192
#define N_TOTAL 4096
#define K_IN    4096
#define LIMBS   2
#define KP      (K_IN * LIMBS)        // 8192

#define BM 128
#define BN 128
#define BKS 32                        // fp16 k-elems per stage
#define NK (KP / BKS)                 // 256
#define STAGES 4
#define PITCH 40                      // smem row pitch in fp16 (32 data + 8 pad)
#define TILE_BYTES (128 * PITCH * 2)  // 10240 B per (A or B) stage tile
#define SMEM_BYTES (STAGES * TILE_BYTES * 2)  // 81920

// ---------------- scratch (device globals: allocation-free) ----------------
__device__ __half g_A[(size_t)M_TOTAL * KP];    // 2-limb fp16 split of x, [M][8192]
__device__ __half g_W[(size_t)N_TOTAL * K_IN];  // sign(W) as fp16, [N][4096]

// ---------------- helpers ----------------
static __device__ __forceinline__ void cpa16(uint32_t dst, const void* src) {
    asm volatile("cp.async.cg.shared.global [%0], [%1], 16;" :: "r"(dst), "l"(src));
}
static __device__ __forceinline__ void ldsm4(uint32_t* r, uint32_t addr) {
    asm volatile("ldmatrix.sync.aligned.m8n8.x4.shared.b16 {%0,%1,%2,%3}, [%4];"
                 : "=r"(r[0]), "=r"(r[1]), "=r"(r[2]), "=r"(r[3]) : "r"(addr));
}
static __device__ __forceinline__ void mma16816(float* c, const uint32_t* a, const uint32_t* b) {
    asm volatile(
        "mma.sync.aligned.m16n8k16.row.col.f32.f16.f16.f32 "
        "{%0,%1,%2,%3}, {%4,%5,%6,%7}, {%8,%9}, {%0,%1,%2,%3};"
        : "+f"(c[0]), "+f"(c[1]), "+f"(c[2]), "+f"(c[3])
        : "r"(a[0]), "r"(a[1]), "r"(a[2]), "r"(a[3]), "r"(b[0]), "r"(b[1]));
}
static __device__ __forceinline__ float sgnf(float z) {
    return (z > 0.f) ? 1.f : ((z < 0.f) ? -1.f : 0.f);
}

// ---------------- prep kernels ----------------
// x = hi + lo, hi = fl16(x), lo = fl16(x - hi); residual <= 2^-22 |x|.
__global__ void prep_x(const float* __restrict__ x) {
    const int t   = blockIdx.x * blockDim.x + threadIdx.x;   // 0..1023
    const int row = blockIdx.y;                               // 0..8191
    const int col = t * 4;
    float4 v = *reinterpret_cast<const float4*>(&x[(size_t)row * K_IN + col]);
    float vv[4] = {v.x, v.y, v.z, v.w};
    __half hi[4], lo[4];
    #pragma unroll
    for (int j = 0; j < 4; j++) {
        hi[j] = __float2half_rn(vv[j]);
        lo[j] = __float2half_rn(vv[j] - __half2float(hi[j]));
    }
    const size_t base = (size_t)row * KP + col;
    *reinterpret_cast<uint2*>(&g_A[base])        = *reinterpret_cast<uint2*>(hi);
    *reinterpret_cast<uint2*>(&g_A[base + K_IN]) = *reinterpret_cast<uint2*>(lo);
}

__global__ void prep_w(const float* __restrict__ w) {
    const size_t idx = (size_t)blockIdx.x * blockDim.x + threadIdx.x;
    float4 v = *reinterpret_cast<const float4*>(&w[idx * 4]);
    float vv[4] = {v.x, v.y, v.z, v.w};
    __half s[4];
    #pragma unroll
    for (int j = 0; j < 4; j++) s[j] = __float2half_rn(sgnf(vv[j]));
    reinterpret_cast<uint2*>(g_W)[idx] = *reinterpret_cast<uint2*>(s);
}

// ---------------- GEMM kernel (mma.sync fp16, fp32 accum) ----------------
__global__ void __launch_bounds__(256)
binlin_gemm(const float* __restrict__ bias, float* __restrict__ out) {
    extern __shared__ __align__(16) char smem[];
    const uint32_t su = (uint32_t)__cvta_generic_to_shared(smem);

    const int tid  = threadIdx.x;
    const int wid  = tid >> 5;
    const int lane = tid & 31;
    const int wm = (wid >> 1) * 32;   // warp m offset 0..96
    const int wn = (wid & 1) * 64;    // warp n offset 0 or 64

    const int m_base = blockIdx.y * BM;
    const int n_base = blockIdx.x * BN;

    float acc[2][8][4];
    #pragma unroll
    for (int mi = 0; mi < 2; mi++)
        #pragma unroll
        for (int ni = 0; ni < 8; ni++)
            #pragma unroll
            for (int j = 0; j < 4; j++) acc[mi][ni][j] = 0.f;

    const int a_row_off = (lane & 7) + ((lane >> 3) & 1) * 8;   // 0..15
    const int a_col_off = (lane >> 4) * 8;                      // 0 or 8
    const int b_row_off = (lane & 7) + (lane >> 4) * 8;         // 0..15
    const int b_col_off = ((lane >> 3) & 1) * 8;                // 0 or 8

    auto load_stage = [&](int s, int kk) {
        const uint32_t abase = su + s * TILE_BYTES;
        const uint32_t bbase = su + STAGES * TILE_BYTES + s * TILE_BYTES;
        const int ka = kk * BKS;              // k' in [0, 8192)
        const int kb = ka & (K_IN - 1);       // W column base (limb-folded)
        #pragma unroll
        for (int i = 0; i < 2; i++) {
            const int cid = tid + i * 256;    // 0..511
            const int row = cid >> 2;
            const int c   = cid & 3;
            cpa16(abase + (row * PITCH + c * 8) * 2,
                  &g_A[(size_t)(m_base + row) * KP + ka + c * 8]);
            cpa16(bbase + (row * PITCH + c * 8) * 2,
                  &g_W[(size_t)(n_base + row) * K_IN + kb + c * 8]);
        }
    };

    auto compute_stage = [&](int s) {
        const uint32_t abase = su + s * TILE_BYTES;
        const uint32_t bbase = su + STAGES * TILE_BYTES + s * TILE_BYTES;
        #pragma unroll
        for (int ks = 0; ks < 2; ks++) {
            uint32_t a[2][4];
            uint32_t b[8][2];
            #pragma unroll
            for (int mi = 0; mi < 2; mi++) {
                uint32_t addr = abase +
                    ((wm + mi * 16 + a_row_off) * PITCH + ks * 16 + a_col_off) * 2;
                ldsm4(a[mi], addr);
            }
            #pragma unroll
            for (int p = 0; p < 4; p++) {
                uint32_t t[4];
                uint32_t addr = bbase +
                    ((wn + p * 16 + b_row_off) * PITCH + ks * 16 + b_col_off) * 2;
                ldsm4(t, addr);
                b[2 * p + 0][0] = t[0]; b[2 * p + 0][1] = t[1];
                b[2 * p + 1][0] = t[2]; b[2 * p + 1][1] = t[3];
            }
            #pragma unroll
            for (int mi = 0; mi < 2; mi++)
                #pragma unroll
                for (int ni = 0; ni < 8; ni++)
                    mma16816(acc[mi][ni], a[mi], b[ni]);
        }
    };

    // ---- pipeline ----
    #pragma unroll
    for (int s = 0; s < STAGES - 1; s++) {
        load_stage(s, s);
        asm volatile("cp.async.commit_group;");
    }
    for (int kk = 0; kk < NK; kk++) {
        const int nx = kk + STAGES - 1;
        if (nx < NK) load_stage(nx & (STAGES - 1), nx);
        asm volatile("cp.async.commit_group;");
        asm volatile("cp.async.wait_group 2;");
        __syncthreads();
        compute_stage(kk & (STAGES - 1));
        __syncthreads();
    }

    // ---- epilogue: z = acc + bias; out = sign(z) ----
    #pragma unroll
    for (int mi = 0; mi < 2; mi++) {
        #pragma unroll
        for (int ni = 0; ni < 8; ni++) {
            const int r = m_base + wm + mi * 16 + (lane >> 2);
            const int c = n_base + wn + ni * 8 + (lane & 3) * 2;
            const float b0 = bias[c];
            const float b1 = bias[c + 1];
            float2 v0, v1;
            v0.x = sgnf(acc[mi][ni][0] + b0);
            v0.y = sgnf(acc[mi][ni][1] + b1);
            v1.x = sgnf(acc[mi][ni][2] + b0);
            v1.y = sgnf(acc[mi][ni][3] + b1);
            *reinterpret_cast<float2*>(&out[(size_t)r * N_TOTAL + c]) = v0;
            *reinterpret_cast<float2*>(&out[(size_t)(r + 8) * N_TOTAL + c]) = v1;
        }
    }
}

// ---------------- host launch ----------------
extern "C" void kernel_launch(void* const* d_in, const int* in_sizes, int n_in,
                              void* d_out, int out_size) {
    const float* x    = (const float*)d_in[0];
    const float* w    = (const float*)d_in[1];
    const float* bias = (const float*)d_in[2];
    float* out = (float*)d_out;

    prep_x<<<dim3(K_IN / (4 * 256), M_TOTAL), 256>>>(x);
    prep_w<<<(int)(((size_t)N_TOTAL * K_IN) / 4 / 256), 256>>>(w);

    cudaFuncSetAttribute(binlin_gemm, cudaFuncAttributeMaxDynamicSharedMemorySize,
                         SMEM_BYTES);
    binlin_gemm<<<dim3(N_TOTAL / BN, M_TOTAL / BM), 256, SMEM_BYTES>>>(bias, out);
}

// round 5
// speedup vs baseline: 6.0702x; 1.7396x over previous
#include <cuda_runtime.h>
#include <cuda_fp16.h>
#include <cstdint>

// ---------------- problem constants ----------------
#define M_TOTAL 8192
#define N_TOTAL 4096
#define K_IN    4096

#define BM 128
#define BN 128
#define BKS 32                        // fp16 k-elems per stage
#define NK (K_IN / BKS)               // 128
#define STAGES 4
#define PITCH 40                      // smem row pitch in fp16 (32 data + 8 pad)
#define TILE_BYTES (128 * PITCH * 2)  // 10240 B per (A or B) stage tile
#define SMEM_BYTES (STAGES * TILE_BYTES * 2)  // 81920

#define TAU 0.125f
#define CAP (1u << 22)                // 4M worklist entries

// ---------------- scratch (device globals: allocation-free) ----------------
__device__ __half g_A[(size_t)M_TOTAL * K_IN];  // hi limb: fl16(x)
__device__ __half g_W[(size_t)N_TOTAL * K_IN];  // sign(W) as fp16
__device__ unsigned g_cnt;
__device__ uint2 g_list[CAP];                   // {m*4096+n, bits(z_hi+bias)}

// ---------------- helpers ----------------
static __device__ __forceinline__ void cpa16(uint32_t dst, const void* src) {
    asm volatile("cp.async.cg.shared.global [%0], [%1], 16;" :: "r"(dst), "l"(src));
}
static __device__ __forceinline__ void ldsm4(uint32_t* r, uint32_t addr) {
    asm volatile("ldmatrix.sync.aligned.m8n8.x4.shared.b16 {%0,%1,%2,%3}, [%4];"
                 : "=r"(r[0]), "=r"(r[1]), "=r"(r[2]), "=r"(r[3]) : "r"(addr));
}
static __device__ __forceinline__ void mma16816(float* c, const uint32_t* a, const uint32_t* b) {
    asm volatile(
        "mma.sync.aligned.m16n8k16.row.col.f32.f16.f16.f32 "
        "{%0,%1,%2,%3}, {%4,%5,%6,%7}, {%8,%9}, {%0,%1,%2,%3};"
        : "+f"(c[0]), "+f"(c[1]), "+f"(c[2]), "+f"(c[3])
        : "r"(a[0]), "r"(a[1]), "r"(a[2]), "r"(a[3]), "r"(b[0]), "r"(b[1]));
}
static __device__ __forceinline__ float sgnf(float z) {
    return (z > 0.f) ? 1.f : ((z < 0.f) ? -1.f : 0.f);
}

// ---------------- prep kernels ----------------
__global__ void zero_cnt() { g_cnt = 0u; }

__global__ void prep_x(const float* __restrict__ x) {
    const int t   = blockIdx.x * blockDim.x + threadIdx.x;   // 0..1023
    const int row = blockIdx.y;
    const int col = t * 4;
    float4 v = *reinterpret_cast<const float4*>(&x[(size_t)row * K_IN + col]);
    float vv[4] = {v.x, v.y, v.z, v.w};
    __half hi[4];
    #pragma unroll
    for (int j = 0; j < 4; j++) hi[j] = __float2half_rn(vv[j]);
    *reinterpret_cast<uint2*>(&g_A[(size_t)row * K_IN + col]) =
        *reinterpret_cast<uint2*>(hi);
}

__global__ void prep_w(const float* __restrict__ w) {
    const size_t idx = (size_t)blockIdx.x * blockDim.x + threadIdx.x;
    float4 v = *reinterpret_cast<const float4*>(&w[idx * 4]);
    float vv[4] = {v.x, v.y, v.z, v.w};
    __half s[4];
    #pragma unroll
    for (int j = 0; j < 4; j++) s[j] = __float2half_rn(sgnf(vv[j]));
    reinterpret_cast<uint2*>(g_W)[idx] = *reinterpret_cast<uint2*>(s);
}

// ---------------- GEMM kernel (hi limb only) ----------------
__global__ void __launch_bounds__(256)
binlin_gemm(const float* __restrict__ bias, float* __restrict__ out) {
    extern __shared__ __align__(16) char smem[];
    const uint32_t su = (uint32_t)__cvta_generic_to_shared(smem);

    const int tid  = threadIdx.x;
    const int wid  = tid >> 5;
    const int lane = tid & 31;
    const int wm = (wid >> 1) * 32;
    const int wn = (wid & 1) * 64;

    const int m_base = blockIdx.y * BM;
    const int n_base = blockIdx.x * BN;

    float acc[2][8][4];
    #pragma unroll
    for (int mi = 0; mi < 2; mi++)
        #pragma unroll
        for (int ni = 0; ni < 8; ni++)
            #pragma unroll
            for (int j = 0; j < 4; j++) acc[mi][ni][j] = 0.f;

    const int a_row_off = (lane & 7) + ((lane >> 3) & 1) * 8;
    const int a_col_off = (lane >> 4) * 8;
    const int b_row_off = (lane & 7) + (lane >> 4) * 8;
    const int b_col_off = ((lane >> 3) & 1) * 8;

    auto load_stage = [&](int s, int kk) {
        const uint32_t abase = su + s * TILE_BYTES;
        const uint32_t bbase = su + STAGES * TILE_BYTES + s * TILE_BYTES;
        const int ka = kk * BKS;
        #pragma unroll
        for (int i = 0; i < 2; i++) {
            const int cid = tid + i * 256;
            const int row = cid >> 2;
            const int c   = cid & 3;
            cpa16(abase + (row * PITCH + c * 8) * 2,
                  &g_A[(size_t)(m_base + row) * K_IN + ka + c * 8]);
            cpa16(bbase + (row * PITCH + c * 8) * 2,
                  &g_W[(size_t)(n_base + row) * K_IN + ka + c * 8]);
        }
    };

    auto compute_stage = [&](int s) {
        const uint32_t abase = su + s * TILE_BYTES;
        const uint32_t bbase = su + STAGES * TILE_BYTES + s * TILE_BYTES;
        #pragma unroll
        for (int ks = 0; ks < 2; ks++) {
            uint32_t a[2][4];
            uint32_t b[8][2];
            #pragma unroll
            for (int mi = 0; mi < 2; mi++) {
                uint32_t addr = abase +
                    ((wm + mi * 16 + a_row_off) * PITCH + ks * 16 + a_col_off) * 2;
                ldsm4(a[mi], addr);
            }
            #pragma unroll
            for (int p = 0; p < 4; p++) {
                uint32_t t[4];
                uint32_t addr = bbase +
                    ((wn + p * 16 + b_row_off) * PITCH + ks * 16 + b_col_off) * 2;
                ldsm4(t, addr);
                b[2 * p + 0][0] = t[0]; b[2 * p + 0][1] = t[1];
                b[2 * p + 1][0] = t[2]; b[2 * p + 1][1] = t[3];
            }
            #pragma unroll
            for (int mi = 0; mi < 2; mi++)
                #pragma unroll
                for (int ni = 0; ni < 8; ni++)
                    mma16816(acc[mi][ni], a[mi], b[ni]);
        }
    };

    #pragma unroll
    for (int s = 0; s < STAGES - 1; s++) {
        load_stage(s, s);
        asm volatile("cp.async.commit_group;");
    }
    for (int kk = 0; kk < NK; kk++) {
        const int nx = kk + STAGES - 1;
        if (nx < NK) load_stage(nx & (STAGES - 1), nx);
        asm volatile("cp.async.commit_group;");
        asm volatile("cp.async.wait_group 2;");
        __syncthreads();
        compute_stage(kk & (STAGES - 1));
        __syncthreads();
    }

    // ---- epilogue: provisional sign + flag near-zero outputs ----
    #pragma unroll
    for (int mi = 0; mi < 2; mi++) {
        #pragma unroll
        for (int ni = 0; ni < 8; ni++) {
            const int r = m_base + wm + mi * 16 + (lane >> 2);
            const int c = n_base + wn + ni * 8 + (lane & 3) * 2;
            const float b0 = bias[c];
            const float b1 = bias[c + 1];
            float z[4];
            z[0] = acc[mi][ni][0] + b0;
            z[1] = acc[mi][ni][1] + b1;
            z[2] = acc[mi][ni][2] + b0;
            z[3] = acc[mi][ni][3] + b1;
            float2 v0, v1;
            v0.x = sgnf(z[0]); v0.y = sgnf(z[1]);
            v1.x = sgnf(z[2]); v1.y = sgnf(z[3]);
            *reinterpret_cast<float2*>(&out[(size_t)r * N_TOTAL + c]) = v0;
            *reinterpret_cast<float2*>(&out[(size_t)(r + 8) * N_TOTAL + c]) = v1;
            #pragma unroll
            for (int j = 0; j < 4; j++) {
                if (fabsf(z[j]) < TAU) {
                    const int rr = r + (j >> 1) * 8;
                    const int cc = c + (j & 1);
                    unsigned pos = atomicAdd(&g_cnt, 1u);
                    if (pos < CAP)
                        g_list[pos] = make_uint2((unsigned)rr * N_TOTAL + cc,
                                                 __float_as_uint(z[j]));
                }
            }
        }
    }
}

// ---------------- fixup kernel: exact lo-residual correction ----------------
__global__ void __launch_bounds__(256)
fixup(const float* __restrict__ x, float* __restrict__ out) {
    const unsigned total = min(g_cnt, CAP);
    const int lane   = threadIdx.x & 31;
    const int warpId = (blockIdx.x * blockDim.x + threadIdx.x) >> 5;
    const int nwarps = (gridDim.x * blockDim.x) >> 5;

    for (unsigned it = warpId; it < total; it += nwarps) {
        const uint2 e = g_list[it];
        const int m = e.x / N_TOTAL;
        const int n = e.x % N_TOTAL;
        const float zhi = __uint_as_float(e.y);

        const float4* xr = reinterpret_cast<const float4*>(x + (size_t)m * K_IN);
        const uint4*  wr = reinterpret_cast<const uint4*>(g_W + (size_t)n * K_IN);

        float s = 0.f;
        #pragma unroll 4
        for (int i = 0; i < 16; i++) {
            const int ch = i * 32 + lane;        // chunk of 8 elems
            float4 x0 = xr[2 * ch];
            float4 x1 = xr[2 * ch + 1];
            uint4  wv = wr[ch];
            const __half2* wh = reinterpret_cast<const __half2*>(&wv);
            float xs[8] = {x0.x, x0.y, x0.z, x0.w, x1.x, x1.y, x1.z, x1.w};
            #pragma unroll
            for (int q = 0; q < 4; q++) {
                float2 wf = __half22float2(wh[q]);
                float xa = xs[2 * q], xb = xs[2 * q + 1];
                float la = xa - __half2float(__float2half_rn(xa));
                float lb = xb - __half2float(__float2half_rn(xb));
                s += la * wf.x + lb * wf.y;
            }
        }
        #pragma unroll
        for (int o = 16; o; o >>= 1) s += __shfl_xor_sync(0xffffffffu, s, o);
        if (lane == 0) out[e.x] = sgnf(zhi + s);
    }
}

// ---------------- host launch ----------------
extern "C" void kernel_launch(void* const* d_in, const int* in_sizes, int n_in,
                              void* d_out, int out_size) {
    const float* x    = (const float*)d_in[0];
    const float* w    = (const float*)d_in[1];
    const float* bias = (const float*)d_in[2];
    float* out = (float*)d_out;

    zero_cnt<<<1, 1>>>();
    prep_x<<<dim3(K_IN / (4 * 256), M_TOTAL), 256>>>(x);
    prep_w<<<(int)(((size_t)N_TOTAL * K_IN) / 4 / 256), 256>>>(w);

    cudaFuncSetAttribute(binlin_gemm, cudaFuncAttributeMaxDynamicSharedMemorySize,
                         SMEM_BYTES);
    binlin_gemm<<<dim3(N_TOTAL / BN, M_TOTAL / BM), 256, SMEM_BYTES>>>(bias, out);

    fixup<<<1024, 256>>>(x, out);
}

// round 6
// speedup vs baseline: 6.4838x; 1.0681x over previous
#include <cuda_runtime.h>
#include <cuda_fp16.h>
#include <cstdint>

// ---------------- problem constants ----------------
#define M_TOTAL 8192
#define N_TOTAL 4096
#define K_IN    4096

#define BM 128
#define BN 128
#define BKS 32                        // fp16 k-elems per stage
#define NK (K_IN / BKS)               // 128
#define STAGES 4
#define PITCH 40                      // smem row pitch in fp16 (32 data + 8 pad)
#define TILE_BYTES (128 * PITCH * 2)  // 10240 B per (A or B) stage tile
#define SMEM_BYTES (STAGES * TILE_BYTES * 2)  // 81920 (x2 CTAs = 160KB < 228KB)

#define TAU 0.125f
#define CAP (1u << 22)                // 4M worklist entries

// ---------------- scratch (device globals: allocation-free) ----------------
__device__ __half g_A[(size_t)M_TOTAL * K_IN];  // hi limb: fl16(x)
__device__ __half g_W[(size_t)N_TOTAL * K_IN];  // sign(W) as fp16
__device__ unsigned g_cnt;
__device__ uint2 g_list[CAP];                   // {m*4096+n, bits(z_hi+bias)}

// ---------------- helpers ----------------
static __device__ __forceinline__ void cpa16(uint32_t dst, const void* src) {
    asm volatile("cp.async.cg.shared.global [%0], [%1], 16;" :: "r"(dst), "l"(src));
}
static __device__ __forceinline__ void ldsm4(uint32_t* r, uint32_t addr) {
    asm volatile("ldmatrix.sync.aligned.m8n8.x4.shared.b16 {%0,%1,%2,%3}, [%4];"
                 : "=r"(r[0]), "=r"(r[1]), "=r"(r[2]), "=r"(r[3]) : "r"(addr));
}
static __device__ __forceinline__ void mma16816(float* c, const uint32_t* a, const uint32_t* b) {
    asm volatile(
        "mma.sync.aligned.m16n8k16.row.col.f32.f16.f16.f32 "
        "{%0,%1,%2,%3}, {%4,%5,%6,%7}, {%8,%9}, {%0,%1,%2,%3};"
        : "+f"(c[0]), "+f"(c[1]), "+f"(c[2]), "+f"(c[3])
        : "r"(a[0]), "r"(a[1]), "r"(a[2]), "r"(a[3]), "r"(b[0]), "r"(b[1]));
}
static __device__ __forceinline__ float sgnf(float z) {
    return (z > 0.f) ? 1.f : ((z < 0.f) ? -1.f : 0.f);
}

// ---------------- prep kernels ----------------
__global__ void zero_cnt() { g_cnt = 0u; }

__global__ void prep_x(const float* __restrict__ x) {
    const int t   = blockIdx.x * blockDim.x + threadIdx.x;   // 0..1023
    const int row = blockIdx.y;
    const int col = t * 4;
    float4 v = *reinterpret_cast<const float4*>(&x[(size_t)row * K_IN + col]);
    float vv[4] = {v.x, v.y, v.z, v.w};
    __half hi[4];
    #pragma unroll
    for (int j = 0; j < 4; j++) hi[j] = __float2half_rn(vv[j]);
    *reinterpret_cast<uint2*>(&g_A[(size_t)row * K_IN + col]) =
        *reinterpret_cast<uint2*>(hi);
}

__global__ void prep_w(const float* __restrict__ w) {
    const size_t idx = (size_t)blockIdx.x * blockDim.x + threadIdx.x;
    float4 v = *reinterpret_cast<const float4*>(&w[idx * 4]);
    float vv[4] = {v.x, v.y, v.z, v.w};
    __half s[4];
    #pragma unroll
    for (int j = 0; j < 4; j++) s[j] = __float2half_rn(sgnf(vv[j]));
    reinterpret_cast<uint2*>(g_W)[idx] = *reinterpret_cast<uint2*>(s);
}

// ---------------- GEMM kernel (hi limb only, 2 CTAs/SM) ----------------
__global__ void __launch_bounds__(256, 2)
binlin_gemm(const float* __restrict__ bias, float* __restrict__ out) {
    extern __shared__ __align__(16) char smem[];
    const uint32_t su = (uint32_t)__cvta_generic_to_shared(smem);

    const int tid  = threadIdx.x;
    const int wid  = tid >> 5;
    const int lane = tid & 31;
    const int wm = (wid >> 1) * 32;
    const int wn = (wid & 1) * 64;

    const int m_base = blockIdx.y * BM;
    const int n_base = blockIdx.x * BN;

    float acc[2][8][4];
    #pragma unroll
    for (int mi = 0; mi < 2; mi++)
        #pragma unroll
        for (int ni = 0; ni < 8; ni++)
            #pragma unroll
            for (int j = 0; j < 4; j++) acc[mi][ni][j] = 0.f;

    const int a_row_off = (lane & 7) + ((lane >> 3) & 1) * 8;
    const int a_col_off = (lane >> 4) * 8;
    const int b_row_off = (lane & 7) + (lane >> 4) * 8;
    const int b_col_off = ((lane >> 3) & 1) * 8;

    auto load_stage = [&](int s, int kk) {
        const uint32_t abase = su + s * TILE_BYTES;
        const uint32_t bbase = su + STAGES * TILE_BYTES + s * TILE_BYTES;
        const int ka = kk * BKS;
        #pragma unroll
        for (int i = 0; i < 2; i++) {
            const int cid = tid + i * 256;
            const int row = cid >> 2;
            const int c   = cid & 3;
            cpa16(abase + (row * PITCH + c * 8) * 2,
                  &g_A[(size_t)(m_base + row) * K_IN + ka + c * 8]);
            cpa16(bbase + (row * PITCH + c * 8) * 2,
                  &g_W[(size_t)(n_base + row) * K_IN + ka + c * 8]);
        }
    };

    auto compute_stage = [&](int s) {
        const uint32_t abase = su + s * TILE_BYTES;
        const uint32_t bbase = su + STAGES * TILE_BYTES + s * TILE_BYTES;
        #pragma unroll
        for (int ks = 0; ks < 2; ks++) {
            uint32_t a[2][4];
            uint32_t b[8][2];
            #pragma unroll
            for (int mi = 0; mi < 2; mi++) {
                uint32_t addr = abase +
                    ((wm + mi * 16 + a_row_off) * PITCH + ks * 16 + a_col_off) * 2;
                ldsm4(a[mi], addr);
            }
            #pragma unroll
            for (int p = 0; p < 4; p++) {
                uint32_t t[4];
                uint32_t addr = bbase +
                    ((wn + p * 16 + b_row_off) * PITCH + ks * 16 + b_col_off) * 2;
                ldsm4(t, addr);
                b[2 * p + 0][0] = t[0]; b[2 * p + 0][1] = t[1];
                b[2 * p + 1][0] = t[2]; b[2 * p + 1][1] = t[3];
            }
            #pragma unroll
            for (int mi = 0; mi < 2; mi++)
                #pragma unroll
                for (int ni = 0; ni < 8; ni++)
                    mma16816(acc[mi][ni], a[mi], b[ni]);
        }
    };

    #pragma unroll
    for (int s = 0; s < STAGES - 1; s++) {
        load_stage(s, s);
        asm volatile("cp.async.commit_group;");
    }
    for (int kk = 0; kk < NK; kk++) {
        const int nx = kk + STAGES - 1;
        if (nx < NK) load_stage(nx & (STAGES - 1), nx);
        asm volatile("cp.async.commit_group;");
        asm volatile("cp.async.wait_group 2;");
        __syncthreads();
        compute_stage(kk & (STAGES - 1));
        __syncthreads();
    }

    // ---- epilogue: provisional sign + flag near-zero outputs ----
    #pragma unroll
    for (int mi = 0; mi < 2; mi++) {
        #pragma unroll
        for (int ni = 0; ni < 8; ni++) {
            const int r = m_base + wm + mi * 16 + (lane >> 2);
            const int c = n_base + wn + ni * 8 + (lane & 3) * 2;
            const float b0 = bias[c];
            const float b1 = bias[c + 1];
            float z[4];
            z[0] = acc[mi][ni][0] + b0;
            z[1] = acc[mi][ni][1] + b1;
            z[2] = acc[mi][ni][2] + b0;
            z[3] = acc[mi][ni][3] + b1;
            float2 v0, v1;
            v0.x = sgnf(z[0]); v0.y = sgnf(z[1]);
            v1.x = sgnf(z[2]); v1.y = sgnf(z[3]);
            *reinterpret_cast<float2*>(&out[(size_t)r * N_TOTAL + c]) = v0;
            *reinterpret_cast<float2*>(&out[(size_t)(r + 8) * N_TOTAL + c]) = v1;
            #pragma unroll
            for (int j = 0; j < 4; j++) {
                if (fabsf(z[j]) < TAU) {
                    const int rr = r + (j >> 1) * 8;
                    const int cc = c + (j & 1);
                    unsigned pos = atomicAdd(&g_cnt, 1u);
                    if (pos < CAP)
                        g_list[pos] = make_uint2((unsigned)rr * N_TOTAL + cc,
                                                 __float_as_uint(z[j]));
                }
            }
        }
    }
}

// ---------------- fixup kernel: exact lo-residual correction ----------------
__global__ void __launch_bounds__(256)
fixup(const float* __restrict__ x, float* __restrict__ out) {
    const unsigned total = min(g_cnt, CAP);
    const int lane   = threadIdx.x & 31;
    const int warpId = (blockIdx.x * blockDim.x + threadIdx.x) >> 5;
    const int nwarps = (gridDim.x * blockDim.x) >> 5;

    for (unsigned it = warpId; it < total; it += nwarps) {
        const uint2 e = g_list[it];
        const int m = e.x / N_TOTAL;
        const int n = e.x % N_TOTAL;
        const float zhi = __uint_as_float(e.y);

        const float4* xr = reinterpret_cast<const float4*>(x + (size_t)m * K_IN);
        const uint4*  wr = reinterpret_cast<const uint4*>(g_W + (size_t)n * K_IN);

        float s = 0.f;
        #pragma unroll 4
        for (int i = 0; i < 16; i++) {
            const int ch = i * 32 + lane;        // chunk of 8 elems
            float4 x0 = xr[2 * ch];
            float4 x1 = xr[2 * ch + 1];
            uint4  wv = wr[ch];
            const __half2* wh = reinterpret_cast<const __half2*>(&wv);
            float xs[8] = {x0.x, x0.y, x0.z, x0.w, x1.x, x1.y, x1.z, x1.w};
            #pragma unroll
            for (int q = 0; q < 4; q++) {
                float2 wf = __half22float2(wh[q]);
                float xa = xs[2 * q], xb = xs[2 * q + 1];
                float la = xa - __half2float(__float2half_rn(xa));
                float lb = xb - __half2float(__float2half_rn(xb));
                s += la * wf.x + lb * wf.y;
            }
        }
        #pragma unroll
        for (int o = 16; o; o >>= 1) s += __shfl_xor_sync(0xffffffffu, s, o);
        if (lane == 0) out[e.x] = sgnf(zhi + s);
    }
}

// ---------------- host launch ----------------
extern "C" void kernel_launch(void* const* d_in, const int* in_sizes, int n_in,
                              void* d_out, int out_size) {
    const float* x    = (const float*)d_in[0];
    const float* w    = (const float*)d_in[1];
    const float* bias = (const float*)d_in[2];
    float* out = (float*)d_out;

    zero_cnt<<<1, 1>>>();
    prep_x<<<dim3(K_IN / (4 * 256), M_TOTAL), 256>>>(x);
    prep_w<<<(int)(((size_t)N_TOTAL * K_IN) / 4 / 256), 256>>>(w);

    cudaFuncSetAttribute(binlin_gemm, cudaFuncAttributeMaxDynamicSharedMemorySize,
                         SMEM_BYTES);
    binlin_gemm<<<dim3(N_TOTAL / BN, M_TOTAL / BM), 256, SMEM_BYTES>>>(bias, out);

    fixup<<<1024, 256>>>(x, out);
}

// round 7
// speedup vs baseline: 7.1444x; 1.1019x over previous
#include <cuda_runtime.h>
#include <cuda_fp16.h>
#include <cstdint>

// ---------------- problem constants ----------------
#define M_TOTAL 8192
#define N_TOTAL 4096
#define K_IN    4096

#define BM 128
#define BN 128
#define BKS 64                        // fp16 k-elems per stage
#define NK (K_IN / BKS)               // 64
#define STAGES 3
#define PITCH 72                      // smem row pitch in fp16 (64 data + 8 pad)
#define TILE_BYTES (128 * PITCH * 2)  // 18432 B per (A or B) stage tile
#define STAGE_BYTES (2 * TILE_BYTES)  // 36864 (A tile + B tile)
#define SMEM_BYTES (STAGES * STAGE_BYTES)  // 110592 (x2 CTAs = 221KB < 228KB)

#define TAU 0.125f
#define CAP (1u << 22)                // 4M worklist entries

// ---------------- scratch (device globals: allocation-free) ----------------
__device__ __half g_A[(size_t)M_TOTAL * K_IN];  // hi limb: fl16(x)
__device__ __half g_W[(size_t)N_TOTAL * K_IN];  // sign(W) as fp16
__device__ unsigned g_cnt;
__device__ uint2 g_list[CAP];                   // {m*4096+n, bits(z_hi+bias)}

// ---------------- helpers ----------------
static __device__ __forceinline__ void cpa16(uint32_t dst, const void* src) {
    asm volatile("cp.async.cg.shared.global [%0], [%1], 16;" :: "r"(dst), "l"(src));
}
static __device__ __forceinline__ void ldsm4(uint32_t* r, uint32_t addr) {
    asm volatile("ldmatrix.sync.aligned.m8n8.x4.shared.b16 {%0,%1,%2,%3}, [%4];"
                 : "=r"(r[0]), "=r"(r[1]), "=r"(r[2]), "=r"(r[3]) : "r"(addr));
}
static __device__ __forceinline__ void mma16816(float* c, const uint32_t* a, const uint32_t* b) {
    asm volatile(
        "mma.sync.aligned.m16n8k16.row.col.f32.f16.f16.f32 "
        "{%0,%1,%2,%3}, {%4,%5,%6,%7}, {%8,%9}, {%0,%1,%2,%3};"
        : "+f"(c[0]), "+f"(c[1]), "+f"(c[2]), "+f"(c[3])
        : "r"(a[0]), "r"(a[1]), "r"(a[2]), "r"(a[3]), "r"(b[0]), "r"(b[1]));
}
static __device__ __forceinline__ float sgnf(float z) {
    return (z > 0.f) ? 1.f : ((z < 0.f) ? -1.f : 0.f);
}

// ---------------- prep kernels ----------------
__global__ void zero_cnt() { g_cnt = 0u; }

__global__ void prep_x(const float* __restrict__ x) {
    const int t   = blockIdx.x * blockDim.x + threadIdx.x;   // 0..1023
    const int row = blockIdx.y;
    const int col = t * 4;
    float4 v = *reinterpret_cast<const float4*>(&x[(size_t)row * K_IN + col]);
    float vv[4] = {v.x, v.y, v.z, v.w};
    __half hi[4];
    #pragma unroll
    for (int j = 0; j < 4; j++) hi[j] = __float2half_rn(vv[j]);
    *reinterpret_cast<uint2*>(&g_A[(size_t)row * K_IN + col]) =
        *reinterpret_cast<uint2*>(hi);
}

__global__ void prep_w(const float* __restrict__ w) {
    const size_t idx = (size_t)blockIdx.x * blockDim.x + threadIdx.x;
    float4 v = *reinterpret_cast<const float4*>(&w[idx * 4]);
    float vv[4] = {v.x, v.y, v.z, v.w};
    __half s[4];
    #pragma unroll
    for (int j = 0; j < 4; j++) s[j] = __float2half_rn(sgnf(vv[j]));
    reinterpret_cast<uint2*>(g_W)[idx] = *reinterpret_cast<uint2*>(s);
}

// ---------------- GEMM kernel (hi limb only, 2 CTAs/SM, 1 sync/iter) ----------------
__global__ void __launch_bounds__(256, 2)
binlin_gemm(const float* __restrict__ bias, float* __restrict__ out) {
    extern __shared__ __align__(16) char smem[];
    const uint32_t su = (uint32_t)__cvta_generic_to_shared(smem);

    const int tid  = threadIdx.x;
    const int wid  = tid >> 5;
    const int lane = tid & 31;
    const int wm = (wid >> 1) * 32;
    const int wn = (wid & 1) * 64;

    const int m_base = blockIdx.y * BM;
    const int n_base = blockIdx.x * BN;

    float acc[2][8][4];
    #pragma unroll
    for (int mi = 0; mi < 2; mi++)
        #pragma unroll
        for (int ni = 0; ni < 8; ni++)
            #pragma unroll
            for (int j = 0; j < 4; j++) acc[mi][ni][j] = 0.f;

    const int a_row_off = (lane & 7) + ((lane >> 3) & 1) * 8;
    const int a_col_off = (lane >> 4) * 8;
    const int b_row_off = (lane & 7) + (lane >> 4) * 8;
    const int b_col_off = ((lane >> 3) & 1) * 8;

    // per-stage layout: [A tile | B tile]
    auto load_stage = [&](int s, int kk) {
        const uint32_t abase = su + s * STAGE_BYTES;
        const uint32_t bbase = abase + TILE_BYTES;
        const int ka = kk * BKS;
        #pragma unroll
        for (int i = 0; i < 4; i++) {
            const int cid = tid + i * 256;        // 0..1023
            const int row = cid >> 3;             // 0..127
            const int c   = cid & 7;              // 0..7 (16B chunks)
            cpa16(abase + row * (PITCH * 2) + c * 16,
                  &g_A[(size_t)(m_base + row) * K_IN + ka + c * 8]);
            cpa16(bbase + row * (PITCH * 2) + c * 16,
                  &g_W[(size_t)(n_base + row) * K_IN + ka + c * 8]);
        }
    };

    auto compute_stage = [&](int s) {
        const uint32_t abase = su + s * STAGE_BYTES;
        const uint32_t bbase = abase + TILE_BYTES;
        #pragma unroll
        for (int ks = 0; ks < 4; ks++) {
            uint32_t a[2][4];
            uint32_t b[8][2];
            #pragma unroll
            for (int mi = 0; mi < 2; mi++) {
                uint32_t addr = abase +
                    ((wm + mi * 16 + a_row_off) * PITCH + ks * 16 + a_col_off) * 2;
                ldsm4(a[mi], addr);
            }
            #pragma unroll
            for (int p = 0; p < 4; p++) {
                uint32_t t[4];
                uint32_t addr = bbase +
                    ((wn + p * 16 + b_row_off) * PITCH + ks * 16 + b_col_off) * 2;
                ldsm4(t, addr);
                b[2 * p + 0][0] = t[0]; b[2 * p + 0][1] = t[1];
                b[2 * p + 1][0] = t[2]; b[2 * p + 1][1] = t[3];
            }
            #pragma unroll
            for (int mi = 0; mi < 2; mi++)
                #pragma unroll
                for (int ni = 0; ni < 8; ni++)
                    mma16816(acc[mi][ni], a[mi], b[ni]);
        }
    };

    // ---- prologue: preload stages 0..STAGES-2 ----
    #pragma unroll
    for (int s = 0; s < STAGES - 1; s++) {
        load_stage(s, s);
        asm volatile("cp.async.commit_group;");
    }

    // ---- mainloop: ONE sync per iteration ----
    // order: wait(data for kk) -> sync (all warps done with stage kk-1) ->
    //        issue loads for kk+STAGES-1 (overwrites stage kk-1: safe) -> compute kk
    for (int kk = 0; kk < NK; kk++) {
        asm volatile("cp.async.wait_group %0;" :: "n"(STAGES - 2));
        __syncthreads();
        const int nx = kk + STAGES - 1;
        if (nx < NK) load_stage(nx % STAGES, nx);
        asm volatile("cp.async.commit_group;");
        compute_stage(kk % STAGES);
    }

    // ---- epilogue: provisional sign + flag near-zero outputs ----
    #pragma unroll
    for (int mi = 0; mi < 2; mi++) {
        #pragma unroll
        for (int ni = 0; ni < 8; ni++) {
            const int r = m_base + wm + mi * 16 + (lane >> 2);
            const int c = n_base + wn + ni * 8 + (lane & 3) * 2;
            const float b0 = bias[c];
            const float b1 = bias[c + 1];
            float z[4];
            z[0] = acc[mi][ni][0] + b0;
            z[1] = acc[mi][ni][1] + b1;
            z[2] = acc[mi][ni][2] + b0;
            z[3] = acc[mi][ni][3] + b1;
            float2 v0, v1;
            v0.x = sgnf(z[0]); v0.y = sgnf(z[1]);
            v1.x = sgnf(z[2]); v1.y = sgnf(z[3]);
            *reinterpret_cast<float2*>(&out[(size_t)r * N_TOTAL + c]) = v0;
            *reinterpret_cast<float2*>(&out[(size_t)(r + 8) * N_TOTAL + c]) = v1;
            #pragma unroll
            for (int j = 0; j < 4; j++) {
                if (fabsf(z[j]) < TAU) {
                    const int rr = r + (j >> 1) * 8;
                    const int cc = c + (j & 1);
                    unsigned pos = atomicAdd(&g_cnt, 1u);
                    if (pos < CAP)
                        g_list[pos] = make_uint2((unsigned)rr * N_TOTAL + cc,
                                                 __float_as_uint(z[j]));
                }
            }
        }
    }
}

// ---------------- fixup kernel: exact lo-residual correction ----------------
__global__ void __launch_bounds__(256)
fixup(const float* __restrict__ x, float* __restrict__ out) {
    const unsigned total = min(g_cnt, CAP);
    const int lane   = threadIdx.x & 31;
    const int warpId = (blockIdx.x * blockDim.x + threadIdx.x) >> 5;
    const int nwarps = (gridDim.x * blockDim.x) >> 5;

    for (unsigned it = warpId; it < total; it += nwarps) {
        const uint2 e = g_list[it];
        const int m = e.x / N_TOTAL;
        const int n = e.x % N_TOTAL;
        const float zhi = __uint_as_float(e.y);

        const float4* xr = reinterpret_cast<const float4*>(x + (size_t)m * K_IN);
        const uint4*  wr = reinterpret_cast<const uint4*>(g_W + (size_t)n * K_IN);

        float s = 0.f;
        #pragma unroll 4
        for (int i = 0; i < 16; i++) {
            const int ch = i * 32 + lane;        // chunk of 8 elems
            float4 x0 = xr[2 * ch];
            float4 x1 = xr[2 * ch + 1];
            uint4  wv = wr[ch];
            const __half2* wh = reinterpret_cast<const __half2*>(&wv);
            float xs[8] = {x0.x, x0.y, x0.z, x0.w, x1.x, x1.y, x1.z, x1.w};
            #pragma unroll
            for (int q = 0; q < 4; q++) {
                float2 wf = __half22float2(wh[q]);
                float xa = xs[2 * q], xb = xs[2 * q + 1];
                float la = xa - __half2float(__float2half_rn(xa));
                float lb = xb - __half2float(__float2half_rn(xb));
                s += la * wf.x + lb * wf.y;
            }
        }
        #pragma unroll
        for (int o = 16; o; o >>= 1) s += __shfl_xor_sync(0xffffffffu, s, o);
        if (lane == 0) out[e.x] = sgnf(zhi + s);
    }
}

// ---------------- host launch ----------------
extern "C" void kernel_launch(void* const* d_in, const int* in_sizes, int n_in,
                              void* d_out, int out_size) {
    const float* x    = (const float*)d_in[0];
    const float* w    = (const float*)d_in[1];
    const float* bias = (const float*)d_in[2];
    float* out = (float*)d_out;

    zero_cnt<<<1, 1>>>();
    prep_x<<<dim3(K_IN / (4 * 256), M_TOTAL), 256>>>(x);
    prep_w<<<(int)(((size_t)N_TOTAL * K_IN) / 4 / 256), 256>>>(w);

    cudaFuncSetAttribute(binlin_gemm, cudaFuncAttributeMaxDynamicSharedMemorySize,
                         SMEM_BYTES);
    binlin_gemm<<<dim3(N_TOTAL / BN, M_TOTAL / BM), 256, SMEM_BYTES>>>(bias, out);

    fixup<<<1024, 256>>>(x, out);
}